// round 1
// baseline (speedup 1.0000x reference)
#include <cuda_runtime.h>
#include <cstdint>

#define N_NODES 20000
#define N_EDGES 320000
#define E_TOT   (N_EDGES + N_NODES)   /* 340000, with self loops */
#define D_IN  32
#define D     128
#define DV    16
#define NV    8
#define D_OUT 8

// ---------------- scratch (static device memory; no allocs allowed) ----------
__device__ float g_hA[N_NODES * D];
__device__ float g_hB[N_NODES * D];
__device__ float g_T [N_NODES * D];
__device__ float g_S [N_NODES * D];
__device__ float g_Hn[N_NODES * D];
__device__ float g_elog[E_TOT * NV];
__device__ float g_ex  [E_TOT * NV];
__device__ float g_m [N_NODES * NV];
__device__ float g_s [N_NODES * NV];
__device__ float g_agg[N_NODES * DV];
__device__ int   g_is64;

// ---------------- dtype detection for edge_index ----------------------------
// int64 little-endian with values < 2^31 => every odd int32 word is 0.
__global__ void detect_kernel(const int* __restrict__ idx) {
    int tid = threadIdx.x;
    int z = (idx[2 * tid + 1] == 0) ? 1 : 0;
    int all = __syncthreads_and(z);
    if (tid == 0) g_is64 = all;
}

__device__ __forceinline__ void load_edge(const void* __restrict__ idx, int e,
                                          int& s, int& d) {
    if (e >= N_EDGES) { s = d = e - N_EDGES; return; }  // self loop
    if (g_is64) {
        const long long* p = (const long long*)idx;
        s = (int)p[e];
        d = (int)p[N_EDGES + e];
    } else {
        const int* p = (const int*)idx;
        s = p[e];
        d = p[N_EDGES + e];
    }
}

// ---------------- tiled GEMM: C[M,128] = act(A[M,K] @ W[K,128] + b) ----------
template <int K, int BK, bool RELU>
__global__ void gemm_relu(const float* __restrict__ A, const float* __restrict__ W,
                          const float* __restrict__ b, float* __restrict__ C, int M) {
    constexpr int BM = 64, BN = 128;
    __shared__ float  As[BK][BM + 1];
    __shared__ float4 Ws4[BK][BN / 4];

    int tid  = threadIdx.x;           // 256 threads
    int tcol = tid & 31;              // col group: cols tcol*4 .. +3
    int trow = tid >> 5;              // row group: rows trow*8 .. +7
    int m0   = blockIdx.x * BM;

    float acc[8][4];
#pragma unroll
    for (int r = 0; r < 8; r++)
#pragma unroll
        for (int c = 0; c < 4; c++) acc[r][c] = 0.f;

    for (int k0 = 0; k0 < K; k0 += BK) {
        // ---- load A tile (BM x BK), store transposed As[k][m]
        constexpr int AF4 = BM * BK / 4;
#pragma unroll
        for (int i = 0; i < (AF4 + 255) / 256; i++) {
            int fidx = tid + i * 256;
            if (fidx < AF4) {
                int rr  = fidx / (BK / 4);
                int k4  = fidx % (BK / 4);
                float4 v = make_float4(0.f, 0.f, 0.f, 0.f);
                int row = m0 + rr;
                if (row < M)
                    v = *reinterpret_cast<const float4*>(&A[(size_t)row * K + k0 + k4 * 4]);
                As[k4 * 4 + 0][rr] = v.x;
                As[k4 * 4 + 1][rr] = v.y;
                As[k4 * 4 + 2][rr] = v.z;
                As[k4 * 4 + 3][rr] = v.w;
            }
        }
        // ---- load W tile (BK x 128)
        constexpr int WF4 = BK * BN / 4;
#pragma unroll
        for (int i = 0; i < (WF4 + 255) / 256; i++) {
            int fidx = tid + i * 256;
            if (fidx < WF4) {
                int kk = fidx / (BN / 4);
                int c4 = fidx % (BN / 4);
                Ws4[kk][c4] = *reinterpret_cast<const float4*>(&W[(size_t)(k0 + kk) * BN + c4 * 4]);
            }
        }
        __syncthreads();

#pragma unroll
        for (int kk = 0; kk < BK; kk++) {
            float4 w = Ws4[kk][tcol];
            float a[8];
#pragma unroll
            for (int r = 0; r < 8; r++) a[r] = As[kk][trow * 8 + r];
#pragma unroll
            for (int r = 0; r < 8; r++) {
                acc[r][0] += a[r] * w.x;
                acc[r][1] += a[r] * w.y;
                acc[r][2] += a[r] * w.z;
                acc[r][3] += a[r] * w.w;
            }
        }
        __syncthreads();
    }

    float4 bias = *reinterpret_cast<const float4*>(&b[tcol * 4]);
#pragma unroll
    for (int r = 0; r < 8; r++) {
        int row = m0 + trow * 8 + r;
        if (row < M) {
            float4 o;
            o.x = acc[r][0] + bias.x;
            o.y = acc[r][1] + bias.y;
            o.z = acc[r][2] + bias.z;
            o.w = acc[r][3] + bias.w;
            if (RELU) {
                o.x = fmaxf(o.x, 0.f); o.y = fmaxf(o.y, 0.f);
                o.z = fmaxf(o.z, 0.f); o.w = fmaxf(o.w, 0.f);
            }
            *reinterpret_cast<float4*>(&C[(size_t)row * BN + tcol * 4]) = o;
        }
    }
}

// ---------------- per-layer init: m = 0 (valid lower bound, logits>=0), s=agg=0
__global__ void init_kernel() {
    int i = blockIdx.x * blockDim.x + threadIdx.x;
    if (i < N_NODES * NV) { g_m[i] = 0.f; g_s[i] = 0.f; }
    if (i < N_NODES * DV) g_agg[i] = 0.f;
}

// ---------------- pass 1: per-edge per-head logits + segment max -------------
// 16 lanes per edge, 2 edges per warp. lane l covers dims [8l, 8l+8).
__global__ void edge_logits(const void* __restrict__ idx) {
    int gw   = (blockIdx.x * blockDim.x + threadIdx.x) >> 5;
    int lane = threadIdx.x & 31;
    int sub  = lane >> 4;
    int l    = lane & 15;
    int e    = gw * 2 + sub;
    bool ok  = (e < E_TOT);

    float v = 0.f;
    int s = 0, d = 0;
    if (ok) {
        load_edge(idx, e, s, d);
        const float4* Tp = reinterpret_cast<const float4*>(&g_T[(size_t)d * D + l * 8]);
        const float4* Sp = reinterpret_cast<const float4*>(&g_S[(size_t)s * D + l * 8]);
        float4 t0 = Tp[0], t1 = Tp[1], s0 = Sp[0], s1 = Sp[1];
        v = t0.x * s0.x + t0.y * s0.y + t0.z * s0.z + t0.w * s0.w
          + t1.x * s1.x + t1.y * s1.y + t1.z * s1.z + t1.w * s1.w;
    }
    v += __shfl_xor_sync(0xffffffffu, v, 1);
    if (ok && (l & 1) == 0) {
        int h = l >> 1;
        g_elog[(size_t)e * NV + h] = v;
        atomicMax(reinterpret_cast<int*>(&g_m[(size_t)d * NV + h]), __float_as_int(v));
    }
}

// ---------------- pass 2: exp + segment sum ---------------------------------
__global__ void edge_softmax(const void* __restrict__ idx) {
    int i = blockIdx.x * blockDim.x + threadIdx.x;
    if (i >= E_TOT * NV) return;
    int e = i >> 3, h = i & 7;
    int s, d;
    load_edge(idx, e, s, d);
    float ex = expf(g_elog[i] - g_m[(size_t)d * NV + h]);
    g_ex[i] = ex;
    atomicAdd(&g_s[(size_t)d * NV + h], ex);
}

// ---------------- pass 3: alpha-weighted head-mean message + segment sum -----
// 16 lanes per edge (lane = dv), 2 edges per warp.
__global__ void edge_aggregate(const void* __restrict__ idx) {
    int gw   = (blockIdx.x * blockDim.x + threadIdx.x) >> 5;
    int lane = threadIdx.x & 31;
    int sub  = lane >> 4;
    int l    = lane & 15;
    int e    = gw * 2 + sub;
    bool ok  = (e < E_TOT);

    int s = 0, d = 0;
    if (ok) load_edge(idx, e, s, d);

    float a = 0.f;
    if (ok && l < 8)
        a = g_ex[(size_t)e * NV + l] / (g_s[(size_t)d * NV + l] + 1e-12f);

    float acc = 0.f;
    int gbase = sub * 16;
#pragma unroll
    for (int h = 0; h < 8; h++) {
        float ah = __shfl_sync(0xffffffffu, a, gbase + h);
        if (ok) acc += g_Hn[(size_t)s * D + h * DV + l] * ah;
    }
    if (ok) atomicAdd(&g_agg[(size_t)d * DV + l], acc * 0.125f);
}

// ---------------- output head: out[M,8] = h[M,128] @ Wout + bout -------------
__global__ void out_kernel(const float* __restrict__ h, const float* __restrict__ W,
                           const float* __restrict__ b, float* __restrict__ out) {
    __shared__ float hs[32][132];
    __shared__ float Wsm[128][8];
    int tid = threadIdx.x;  // 256
    int m0  = blockIdx.x * 32;

#pragma unroll
    for (int i = 0; i < 4; i++) {
        int f = tid + i * 256;           // 1024 W elements
        Wsm[f >> 3][f & 7] = W[f];
    }
#pragma unroll
    for (int i = 0; i < 4; i++) {
        int f4  = tid + i * 256;         // 1024 float4 of h tile
        int row = f4 >> 5;
        int c4  = f4 & 31;
        float4 v = make_float4(0.f, 0.f, 0.f, 0.f);
        if (m0 + row < N_NODES)
            v = *reinterpret_cast<const float4*>(&h[(size_t)(m0 + row) * 128 + c4 * 4]);
        *reinterpret_cast<float4*>(&hs[row][c4 * 4]) = v;
    }
    __syncthreads();

    int row = tid >> 3, col = tid & 7;
    float acc = b[col];
#pragma unroll 8
    for (int k = 0; k < 128; k++) acc += hs[row][k] * Wsm[k][col];
    if (m0 + row < N_NODES) out[(size_t)(m0 + row) * 8 + col] = acc;
}

// ---------------- launch ------------------------------------------------------
extern "C" void kernel_launch(void* const* d_in, const int* in_sizes, int n_in,
                              void* d_out, int out_size) {
    const float* x    = (const float*)d_in[0];
    const void*  ei   = d_in[1];
    const float* W1   = (const float*)d_in[2];
    const float* b1   = (const float*)d_in[3];
    const float* W2   = (const float*)d_in[4];
    const float* b2   = (const float*)d_in[5];
    const float* Wout = (const float*)d_in[6];
    const float* bout = (const float*)d_in[7];
    float* out = (float*)d_out;

    float *hA, *hB, *T, *S, *Hn, *agg;
    cudaGetSymbolAddress((void**)&hA, g_hA);
    cudaGetSymbolAddress((void**)&hB, g_hB);
    cudaGetSymbolAddress((void**)&T,  g_T);
    cudaGetSymbolAddress((void**)&S,  g_S);
    cudaGetSymbolAddress((void**)&Hn, g_Hn);
    cudaGetSymbolAddress((void**)&agg, g_agg);

    const int GEMM_BLOCKS = (N_NODES + 63) / 64;        // 313
    const int EDGE_BLOCKS = (E_TOT * 16 + 255) / 256;   // 21250
    const int SM_BLOCKS   = (E_TOT * NV + 255) / 256;   // 10625
    const int INIT_BLOCKS = (N_NODES * DV + 255) / 256; // 1250

    detect_kernel<<<1, 256>>>((const int*)ei);

    // embedding MLP
    gemm_relu<32, 32, true><<<GEMM_BLOCKS, 256>>>(x,  W1, b1, hB, N_NODES);
    gemm_relu<128, 32, true><<<GEMM_BLOCKS, 256>>>(hB, W2, b2, hA, N_NODES);

    float* h     = hA;
    float* hnext = hB;
    for (int l = 0; l < 2; l++) {
        int base = 8 + l * 8;
        const float* Wt = (const float*)d_in[base + 0];
        const float* bt = (const float*)d_in[base + 1];
        const float* Ws = (const float*)d_in[base + 2];
        const float* bs = (const float*)d_in[base + 3];
        const float* Wh = (const float*)d_in[base + 4];
        const float* bh = (const float*)d_in[base + 5];
        const float* Wo = (const float*)d_in[base + 6];
        const float* bo = (const float*)d_in[base + 7];

        gemm_relu<128, 32, true><<<GEMM_BLOCKS, 256>>>(h, Wt, bt, T,  N_NODES);
        gemm_relu<128, 32, true><<<GEMM_BLOCKS, 256>>>(h, Ws, bs, S,  N_NODES);
        gemm_relu<128, 32, true><<<GEMM_BLOCKS, 256>>>(h, Wh, bh, Hn, N_NODES);

        init_kernel<<<INIT_BLOCKS, 256>>>();
        edge_logits   <<<EDGE_BLOCKS, 256>>>(ei);
        edge_softmax  <<<SM_BLOCKS,   256>>>(ei);
        edge_aggregate<<<EDGE_BLOCKS, 256>>>(ei);

        gemm_relu<16, 16, true><<<GEMM_BLOCKS, 256>>>(agg, Wo, bo, hnext, N_NODES);

        float* t = h; h = hnext; hnext = t;
    }

    out_kernel<<<(N_NODES + 31) / 32, 256>>>(h, Wout, bout, out);
}